// round 14
// baseline (speedup 1.0000x reference)
#include <cuda_runtime.h>
#include <cuda_bf16.h>
#include <stdint.h>

#define TT 256
#define BB 64
#define HH 512
#define RC_CTAS 128

typedef unsigned long long ull;

// -------- scratch (__device__ globals) --------
static __device__ float g_gx[(size_t)8 * TT * BB * HH];      // [dg][t][b][h]
static __device__ float g_out0[(size_t)TT * BB * 2 * HH];    // [t][b][2H]
static __device__ float g_gates[8 * BB * HH];                // [dg][b][h]
static __device__ uint32_t g_Ah[8 * BB * 256];               // [dg][b][kpair] bf16x2 hi
static __device__ uint32_t g_Al[8 * BB * 256];               // [dg][b][kpair] bf16x2 lo
static __device__ unsigned g_bar_cnt[8 * 32];                // 8 counters, 128B apart
static __device__ unsigned g_bar_gen;

// -------------------- helpers --------------------
__device__ __forceinline__ void cp_async16(uint32_t s, const void* g) {
    asm volatile("cp.async.cg.shared.global [%0], [%1], 16;" :: "r"(s), "l"(g));
}
__device__ __forceinline__ float fsig(float x) {
    return __fdividef(1.f, 1.f + __expf(-x));
}
__device__ __forceinline__ float ftanh(float x) {
    return 2.f * fsig(2.f * x) - 1.f;
}
__device__ __forceinline__ void mma_bf16(float* d, const uint32_t* a, const uint32_t* b) {
    asm volatile(
        "mma.sync.aligned.m16n8k16.row.col.f32.bf16.bf16.f32 "
        "{%0,%1,%2,%3}, {%4,%5,%6,%7}, {%8,%9}, {%0,%1,%2,%3};"
        : "+f"(d[0]), "+f"(d[1]), "+f"(d[2]), "+f"(d[3])
        : "r"(a[0]), "r"(a[1]), "r"(a[2]), "r"(a[3]), "r"(b[0]), "r"(b[1]));
}
__device__ __forceinline__ void bsplit(float a, uint16_t& h, uint16_t& l) {
    __nv_bfloat16 bh = __float2bfloat16(a);
    float r = a - __bfloat162float(bh);
    __nv_bfloat16 bl = __float2bfloat16(r);
    h = *reinterpret_cast<uint16_t*>(&bh);
    l = *reinterpret_cast<uint16_t*>(&bl);
}
__device__ __forceinline__ uint32_t pack2(uint16_t lo, uint16_t hi) {
    return (uint32_t)lo | ((uint32_t)hi << 16);
}
__device__ __forceinline__ unsigned ld_acq(const unsigned* p) {
    unsigned v;
    asm volatile("ld.acquire.gpu.global.u32 %0, [%1];" : "=r"(v) : "l"(p) : "memory");
    return v;
}

// -------------------- barrier reset --------------------
__global__ void zero_bar_kernel() {
    int i = threadIdx.x;
    if (i < 8 * 32) g_bar_cnt[i] = 0;
    if (i == 0) g_bar_gen = 0;
}

// -------------------- gx GEMM: bf16x3 (verbatim R13) --------------------
template<int K>
__global__ __launch_bounds__(128)
void gx_gemm_kernel(const float* __restrict__ X,
                    const float* __restrict__ Noise,
                    const float* __restrict__ W,
                    const float* __restrict__ bih,
                    const float* __restrict__ bhh)
{
    const int dg = blockIdx.z;
    const int mt = blockIdx.y;
    const int nt = blockIdx.x;
    const int tid = threadIdx.x;

    __shared__ uint32_t Ah[2][64][12];
    __shared__ uint32_t Al[2][64][12];
    __shared__ uint32_t Bhs[2][8][72];
    __shared__ uint32_t Bls[2][8][72];

    const float* Xbase = (K == 1024) ? (const float*)g_out0 : X;
    const float* Xp = Xbase + (size_t)mt * BB * K;
    const float* Np = Noise + (size_t)dg * BB * K;
    const float* Wp = W + (size_t)dg * K * HH + nt * 64;

    const int a_lm = tid >> 2;
    const int a_c  = tid & 3;
    const int b_kp = tid >> 4;
    const int b_ln = (tid & 15) * 4;

    const int wid = tid >> 5;
    const int wm = wid >> 1;
    const int wn = wid & 1;
    const int lane = tid & 31;
    const int gid = lane >> 2;
    const int t4 = lane & 3;

    float acc[2][4][4];
    #pragma unroll
    for (int i = 0; i < 2; i++)
        #pragma unroll
        for (int j = 0; j < 4; j++)
            #pragma unroll
            for (int q = 0; q < 4; q++) acc[i][j][q] = 0.f;

    float4 xv0, xv1, nv0, nv1, wv0, wv1;
    auto ldg_chunk = [&](int k0) {
        xv0 = *reinterpret_cast<const float4*>(Xp + (size_t)a_lm * K + k0 + a_c * 4);
        nv0 = *reinterpret_cast<const float4*>(Np + (size_t)a_lm * K + k0 + a_c * 4);
        xv1 = *reinterpret_cast<const float4*>(Xp + (size_t)(a_lm + 32) * K + k0 + a_c * 4);
        nv1 = *reinterpret_cast<const float4*>(Np + (size_t)(a_lm + 32) * K + k0 + a_c * 4);
        wv0 = *reinterpret_cast<const float4*>(Wp + (size_t)(k0 + 2 * b_kp) * HH + b_ln);
        wv1 = *reinterpret_cast<const float4*>(Wp + (size_t)(k0 + 2 * b_kp + 1) * HH + b_ln);
    };
    auto sts_chunk = [&](int buf) {
        float p[4];
        uint16_t ph[4], pl[4];
        p[0] = xv0.x * nv0.x; p[1] = xv0.y * nv0.y; p[2] = xv0.z * nv0.z; p[3] = xv0.w * nv0.w;
        #pragma unroll
        for (int i = 0; i < 4; i++) bsplit(p[i], ph[i], pl[i]);
        Ah[buf][a_lm][2 * a_c]     = pack2(ph[0], ph[1]);
        Ah[buf][a_lm][2 * a_c + 1] = pack2(ph[2], ph[3]);
        Al[buf][a_lm][2 * a_c]     = pack2(pl[0], pl[1]);
        Al[buf][a_lm][2 * a_c + 1] = pack2(pl[2], pl[3]);
        p[0] = xv1.x * nv1.x; p[1] = xv1.y * nv1.y; p[2] = xv1.z * nv1.z; p[3] = xv1.w * nv1.w;
        #pragma unroll
        for (int i = 0; i < 4; i++) bsplit(p[i], ph[i], pl[i]);
        Ah[buf][a_lm + 32][2 * a_c]     = pack2(ph[0], ph[1]);
        Ah[buf][a_lm + 32][2 * a_c + 1] = pack2(ph[2], ph[3]);
        Al[buf][a_lm + 32][2 * a_c]     = pack2(pl[0], pl[1]);
        Al[buf][a_lm + 32][2 * a_c + 1] = pack2(pl[2], pl[3]);
        float w0[4] = {wv0.x, wv0.y, wv0.z, wv0.w};
        float w1[4] = {wv1.x, wv1.y, wv1.z, wv1.w};
        #pragma unroll
        for (int j = 0; j < 4; j++) {
            uint16_t h0, l0, h1, l1;
            bsplit(w0[j], h0, l0);
            bsplit(w1[j], h1, l1);
            Bhs[buf][b_kp][b_ln + j] = pack2(h0, h1);
            Bls[buf][b_kp][b_ln + j] = pack2(l0, l1);
        }
    };

    const int NC = K / 16;
    ldg_chunk(0);
    sts_chunk(0);
    __syncthreads();

    #pragma unroll 1
    for (int ch = 0; ch < NC; ++ch) {
        if (ch + 1 < NC) ldg_chunk((ch + 1) * 16);

        const int cur = ch & 1;
        uint32_t aH[2][4], aL[2][4];
        #pragma unroll
        for (int mt2 = 0; mt2 < 2; mt2++) {
            const int r0 = wm * 32 + mt2 * 16 + gid;
            const int r1 = r0 + 8;
            aH[mt2][0] = Ah[cur][r0][t4];
            aH[mt2][1] = Ah[cur][r1][t4];
            aH[mt2][2] = Ah[cur][r0][t4 + 4];
            aH[mt2][3] = Ah[cur][r1][t4 + 4];
            aL[mt2][0] = Al[cur][r0][t4];
            aL[mt2][1] = Al[cur][r1][t4];
            aL[mt2][2] = Al[cur][r0][t4 + 4];
            aL[mt2][3] = Al[cur][r1][t4 + 4];
        }
        uint32_t bH[4][2], bL[4][2];
        #pragma unroll
        for (int n2 = 0; n2 < 4; n2++) {
            const int nb = wn * 32 + n2 * 8 + gid;
            bH[n2][0] = Bhs[cur][t4][nb];
            bH[n2][1] = Bhs[cur][t4 + 4][nb];
            bL[n2][0] = Bls[cur][t4][nb];
            bL[n2][1] = Bls[cur][t4 + 4][nb];
        }
        #pragma unroll
        for (int mt2 = 0; mt2 < 2; mt2++)
            #pragma unroll
            for (int n2 = 0; n2 < 4; n2++) {
                mma_bf16(acc[mt2][n2], aH[mt2], bH[n2]);
                mma_bf16(acc[mt2][n2], aH[mt2], bL[n2]);
                mma_bf16(acc[mt2][n2], aL[mt2], bH[n2]);
            }

        if (ch + 1 < NC) {
            sts_chunk((ch + 1) & 1);
            __syncthreads();
        }
    }

    float* Cp = g_gx + ((size_t)dg * TT + mt) * BB * HH;
    #pragma unroll
    for (int mt2 = 0; mt2 < 2; mt2++) {
        #pragma unroll
        for (int n2 = 0; n2 < 4; n2++) {
            const int b0 = wm * 32 + mt2 * 16 + gid;
            const int h0 = nt * 64 + wn * 32 + n2 * 8 + 2 * t4;
            float bx = bih[dg * HH + h0]     + bhh[dg * HH + h0];
            float by = bih[dg * HH + h0 + 1] + bhh[dg * HH + h0 + 1];
            *reinterpret_cast<float2*>(Cp + (size_t)b0 * HH + h0) =
                make_float2(acc[mt2][n2][0] + bx, acc[mt2][n2][1] + by);
            *reinterpret_cast<float2*>(Cp + (size_t)(b0 + 8) * HH + h0) =
                make_float2(acc[mt2][n2][2] + bx, acc[mt2][n2][3] + by);
        }
    }
}

// -------------------- persistent recurrence v4 --------------------------
// Same decomposition as R13; tree barrier + 16 double-k chunks.
// smem: Bh/Bl [256][40] (80KB) + A ring 3 x [2 ksub][hi/lo 768][pad12] (36KB)
__global__ __launch_bounds__(256, 1)
void recur_kernel(const float* __restrict__ Whh,
                  const float* __restrict__ NoiseH,
                  const float* __restrict__ mask,
                  float* __restrict__ outp,
                  int layer,
                  float* __restrict__ hn,
                  float* __restrict__ cn)
{
    extern __shared__ __align__(16) uint32_t smem_dyn[];
    uint32_t* Bh = smem_dyn;                 // [256][40]
    uint32_t* Bl = Bh + 256 * 40;            // [256][40]
    uint32_t* Ar = Bl + 256 * 40;            // ring: 3 x 3072 u32

    const int cta = blockIdx.x;
    const int dg  = cta >> 4;
    const int d   = dg >> 2;
    const int nt  = cta & 15;
    const int pb  = cta & 63;
    const int tid = threadIdx.x;

    float* op = (layer == 0) ? (float*)g_out0 : outp;

    // ---- startup: split W slice into packed bf16x2 hi/lo smem ----
    {
        const float* Wp = Whh + (size_t)dg * HH * HH + nt * 32;
        for (int i = tid; i < 256 * 32; i += 256) {
            int kp = i >> 5;
            int n  = i & 31;
            float w0 = Wp[(size_t)(2 * kp) * HH + n];
            float w1 = Wp[(size_t)(2 * kp + 1) * HH + n];
            uint16_t h0, l0, h1, l1;
            bsplit(w0, h0, l0);
            bsplit(w1, h1, l1);
            Bh[kp * 40 + n] = pack2(h0, h1);
            Bl[kp * 40 + n] = pack2(l0, l1);
        }
    }
    // ---- zero A slice (h0 = 0) ----
    #pragma unroll
    for (int i = 0; i < 4; i++) {
        g_Ah[cta * 1024 + tid + i * 256] = 0;
        g_Al[cta * 1024 + tid + i * 256] = 0;
    }

    // ---- tree grid barrier (8 spread counters + gen; monotonic) ----
    unsigned bar_n = 0;
    unsigned* my_cnt = &g_bar_cnt[(cta & 7) * 32];
    auto grid_bar = [&]() {
        __syncthreads();
        ++bar_n;
        if (tid == 0) {
            asm volatile("red.release.gpu.global.add.u32 [%0], %1;"
                         :: "l"(my_cnt), "r"(1u) : "memory");
            if (cta == 0) {
                #pragma unroll 1
                for (int i = 0; i < 8; i++) {
                    const unsigned tgt = 16u * bar_n;
                    while (ld_acq(&g_bar_cnt[i * 32]) < tgt) __nanosleep(64);
                }
                asm volatile("st.release.gpu.global.u32 [%0], %1;"
                             :: "l"(&g_bar_gen), "r"(bar_n) : "memory");
            } else {
                while (ld_acq(&g_bar_gen) < bar_n) __nanosleep(128);
            }
        }
        __syncthreads();
    };

    grid_bar();

    // fragment ids
    const int wid = tid >> 5;
    const int wm = wid >> 1;                 // m0 = 16*wm
    const int wn = wid & 1;                  // n-group 16*wn
    const int lane = tid & 31;
    const int gid = lane >> 2;
    const int t4 = lane & 3;
    const int m0 = wm * 16;
    const int n0q = wn * 16;

    // cp.async staging ids (per chunk: 2 x 16B per thread, ksubs 0/1)
    const int cs_sel  = tid >> 7;            // 0 = hi, 1 = lo
    const int cs_b    = (tid & 127) >> 1;
    const int cs_half = tid & 1;
    const uint32_t ar_u32 = (uint32_t)__cvta_generic_to_shared(Ar);
    const uint32_t* cs_src_base =
        (cs_sel ? g_Al : g_Ah) + ((size_t)dg * BB + cs_b) * 256 + 4 * cs_half;
    const uint32_t cs_dst_off = (uint32_t)(cs_sel * 768 + cs_b * 12 + 4 * cs_half) * 4;

    // pointwise state in registers (h = 2*tid, 2*tid+1 of (d, pb))
    float2 hreg = make_float2(0.f, 0.f);
    float2 creg = make_float2(0.f, 0.f);

    for (int step = 0; step < TT; ++step) {
        const int t = (d == 0) ? step : (TT - 1 - step);

        // gx prefetch for epilogue
        const float* gxp = g_gx + ((size_t)dg * TT + t) * BB * HH;
        float2 gxb[2][2];
        #pragma unroll
        for (int n2 = 0; n2 < 2; n2++) {
            const int col = nt * 32 + n0q + n2 * 8 + 2 * t4;
            gxb[n2][0] = *reinterpret_cast<const float2*>(gxp + (size_t)(m0 + gid) * HH + col);
            gxb[n2][1] = *reinterpret_cast<const float2*>(gxp + (size_t)(m0 + gid + 8) * HH + col);
        }

        // ---- GEMM: 16 chunks of 16 kpairs, 3-stage cp.async ring ----
        #pragma unroll
        for (int p = 0; p < 2; p++) {
            cp_async16(ar_u32 + (uint32_t)p * 12288 + 0 * 6144 + cs_dst_off,
                       cs_src_base + p * 16);
            cp_async16(ar_u32 + (uint32_t)p * 12288 + 1 * 6144 + cs_dst_off,
                       cs_src_base + p * 16 + 8);
            asm volatile("cp.async.commit_group;");
        }

        float acc[2][4];
        #pragma unroll
        for (int n2 = 0; n2 < 2; n2++)
            #pragma unroll
            for (int q = 0; q < 4; q++) acc[n2][q] = 0.f;

        #pragma unroll 1
        for (int ch = 0; ch < 16; ++ch) {
            asm volatile("cp.async.wait_group 1;");
            __syncthreads();

            const uint32_t* stage = Ar + (ch % 3) * 3072;
            #pragma unroll
            for (int kk = 0; kk < 2; kk++) {
                const uint32_t* Ahs = stage + kk * 1536;
                const uint32_t* Als = Ahs + 768;

                uint32_t aH[4], aL[4];
                const int r0 = (m0 + gid) * 12;
                const int r1 = (m0 + gid + 8) * 12;
                aH[0] = Ahs[r0 + t4];
                aH[1] = Ahs[r1 + t4];
                aH[2] = Ahs[r0 + t4 + 4];
                aH[3] = Ahs[r1 + t4 + 4];
                aL[0] = Als[r0 + t4];
                aL[1] = Als[r1 + t4];
                aL[2] = Als[r0 + t4 + 4];
                aL[3] = Als[r1 + t4 + 4];

                const int kprow0 = (16 * ch + 8 * kk + t4) * 40;
                const int kprow1 = kprow0 + 4 * 40;
                #pragma unroll
                for (int n2 = 0; n2 < 2; n2++) {
                    const int bn = n0q + n2 * 8 + gid;
                    uint32_t bHf[2], bLf[2];
                    bHf[0] = Bh[kprow0 + bn];
                    bHf[1] = Bh[kprow1 + bn];
                    bLf[0] = Bl[kprow0 + bn];
                    bLf[1] = Bl[kprow1 + bn];
                    mma_bf16(acc[n2], aH, bHf);
                    mma_bf16(acc[n2], aH, bLf);
                    mma_bf16(acc[n2], aL, bHf);
                }
            }

            if (ch + 2 < 16) {
                const uint32_t dst = ar_u32 + (uint32_t)((ch + 2) % 3) * 12288 + cs_dst_off;
                cp_async16(dst,        cs_src_base + (size_t)(ch + 2) * 16);
                cp_async16(dst + 6144, cs_src_base + (size_t)(ch + 2) * 16 + 8);
            }
            asm volatile("cp.async.commit_group;");
        }

        // ---- epilogue: gates[dg][b][h] = acc + gx ----
        #pragma unroll
        for (int n2 = 0; n2 < 2; n2++) {
            const int col = nt * 32 + n0q + n2 * 8 + 2 * t4;
            *reinterpret_cast<float2*>(g_gates + ((size_t)dg * BB + m0 + gid) * HH + col) =
                make_float2(acc[n2][0] + gxb[n2][0].x, acc[n2][1] + gxb[n2][0].y);
            *reinterpret_cast<float2*>(g_gates + ((size_t)dg * BB + m0 + gid + 8) * HH + col) =
                make_float2(acc[n2][2] + gxb[n2][1].x, acc[n2][3] + gxb[n2][1].y);
        }

        grid_bar();

        // ---- pointwise: (d, pb), h = 2*tid ----
        {
            const int h = 2 * tid;
            const float* gb = g_gates + ((size_t)(d * 4) * BB + pb) * HH + h;
            const size_t gs = (size_t)BB * HH;
            float2 gi = *reinterpret_cast<const float2*>(gb);
            float2 gf = *reinterpret_cast<const float2*>(gb + gs);
            float2 gg = *reinterpret_cast<const float2*>(gb + 2 * gs);
            float2 go = *reinterpret_cast<const float2*>(gb + 3 * gs);

            const float mt = mask[t * BB + pb];

            float2 hm, cm;
            {
                float cnew = fsig(gf.x) * creg.x + fsig(gi.x) * ftanh(gg.x);
                float hnew = fsig(go.x) * ftanh(cnew);
                hm.x = hnew * mt + hreg.x * (1.f - mt);
                cm.x = cnew * mt + creg.x * (1.f - mt);
            }
            {
                float cnew = fsig(gf.y) * creg.y + fsig(gi.y) * ftanh(gg.y);
                float hnew = fsig(go.y) * ftanh(cnew);
                hm.y = hnew * mt + hreg.y * (1.f - mt);
                cm.y = cnew * mt + creg.y * (1.f - mt);
            }
            hreg = hm; creg = cm;

            // A(step+1) = h*noise, split into packed bf16x2 hi/lo
            #pragma unroll
            for (int g = 0; g < 4; g++) {
                const int dgp = d * 4 + g;
                float2 nz = *reinterpret_cast<const float2*>(
                    NoiseH + ((size_t)dgp * BB + pb) * HH + h);
                float v0 = hm.x * nz.x;
                float v1 = hm.y * nz.y;
                uint16_t h0, l0, h1, l1;
                bsplit(v0, h0, l0);
                bsplit(v1, h1, l1);
                const size_t ai = ((size_t)dgp * BB + pb) * 256 + tid;
                g_Ah[ai] = pack2(h0, h1);
                g_Al[ai] = pack2(l0, l1);
            }

            *reinterpret_cast<float2*>(op + (size_t)t * BB * 2 * HH +
                                       (size_t)pb * 2 * HH + d * HH + h) = hm;

            if (step == TT - 1) {
                const size_t oi = ((size_t)(layer * 2 + d) * BB + pb) * HH + h;
                *reinterpret_cast<float2*>(hn + oi) = hm;
                *reinterpret_cast<float2*>(cn + oi) = cm;
            }
        }

        grid_bar();
    }
}

// -------------------- launch --------------------
extern "C" void kernel_launch(void* const* d_in, const int* in_sizes, int n_in,
                              void* d_out, int out_size)
{
    const float* x      = (const float*)d_in[0];
    const float* mask   = (const float*)d_in[1];
    const float* w_ih0  = (const float*)d_in[2];
    const float* w_hh0  = (const float*)d_in[3];
    const float* b_ih0  = (const float*)d_in[4];
    const float* b_hh0  = (const float*)d_in[5];
    const float* n_in0  = (const float*)d_in[6];
    const float* n_hid0 = (const float*)d_in[7];
    const float* w_ih1  = (const float*)d_in[8];
    const float* w_hh1  = (const float*)d_in[9];
    const float* b_ih1  = (const float*)d_in[10];
    const float* b_hh1  = (const float*)d_in[11];
    const float* n_in1  = (const float*)d_in[12];
    const float* n_hid1 = (const float*)d_in[13];

    float* out  = (float*)d_out;
    float* hn   = out + (size_t)TT * BB * 2 * HH;
    float* cn   = hn + (size_t)4 * BB * HH;

    // smem: Bh/Bl 2*256*40*4 = 81920 B + ring 3*3072*4 = 36864 B
    const int recur_smem = 81920 + 36864;
    static bool attr_set = false;
    if (!attr_set) {
        cudaFuncSetAttribute(recur_kernel,
                             cudaFuncAttributeMaxDynamicSharedMemorySize, recur_smem);
        attr_set = true;
    }

    dim3 gxgrid(HH / 64, TT, 8);

    // layer 0
    gx_gemm_kernel<512><<<gxgrid, 128>>>(x, n_in0, w_ih0, b_ih0, b_hh0);
    zero_bar_kernel<<<1, 256>>>();
    recur_kernel<<<RC_CTAS, 256, recur_smem>>>(w_hh0, n_hid0, mask, out, 0, hn, cn);

    // layer 1
    gx_gemm_kernel<1024><<<gxgrid, 128>>>(nullptr, n_in1, w_ih1, b_ih1, b_hh1);
    zero_bar_kernel<<<1, 256>>>();
    recur_kernel<<<RC_CTAS, 256, recur_smem>>>(w_hh1, n_hid1, mask, out, 1, hn, cn);
}